// round 4
// baseline (speedup 1.0000x reference)
#include <cuda_runtime.h>
#include <cstdint>

// ---------------- problem constants ----------------
#define NN      10000      // nodes
#define NG      2000       // genes (K)
#define ND      301        // embed dim
#define NDP     320        // padded embed dim (5 * 64)
#define NE      320000     // edges
#define NHEADS  4
#define HDIM    12
#define TILE_PER_NODE (NHEADS * ND * HDIM)   // 14448
#define OUT_TILE_ELEMS ((size_t)NN * TILE_PER_NODE)  // 144,480,000
// embeddings follow the tiled output
#define EMB_OFF OUT_TILE_ELEMS

// ---------------- device scratch (static, allocation-free) ----------------
__device__ float g_Wp[NG * NDP];        // zero-padded W  (2.56 MB)
__device__ float g_xw[(size_t)NN * NDP];// x @ Wp         (12.8 MB)
__device__ float g_deg[NN];
__device__ float g_dis[NN];
__device__ int   g_cnt[NN];
__device__ int   g_off[NN + 1];
__device__ int   g_cur[NN];
__device__ int   g_src[NE];
__device__ float g_nrm[NE];
__device__ int   g_is64;                // 1 if edge_index is int64, 0 if int32

// ---------------- edge-index dtype detection ----------------
// The reference asks for int64 but JAX without x64 silently emits int32.
// Interpreting the first 4096 entries as int64: genuine int64 indices are all
// in [0, NN); int32 data reinterpreted as int64 packs two random indices into
// one word -> value >= 2^32 with overwhelming probability.
__global__ void k_detect(const void* __restrict__ ei) {
    __shared__ int bad;
    if (threadIdx.x == 0) bad = 0;
    __syncthreads();
    const long long* p = (const long long*)ei;
    for (int i = threadIdx.x; i < 4096; i += blockDim.x) {
        long long v = p[i];
        if (v < 0 || v >= NN) bad = 1;
    }
    __syncthreads();
    if (threadIdx.x == 0) g_is64 = bad ? 0 : 1;
}

__device__ __forceinline__ int edge_at(const void* __restrict__ ei, int pos) {
    int v = g_is64 ? (int)((const long long*)ei)[pos]
                   : ((const int*)ei)[pos];
    // defensive clamp: a mis-detect becomes a rel_err failure, not a crash
    v = v < 0 ? 0 : (v >= NN ? NN - 1 : v);
    return v;
}

// ---------------- kernels ----------------

// pad W [2000,301] -> g_Wp [2000,320] (zeros in pad cols)
__global__ void k_padW(const float* __restrict__ W) {
    int idx = blockIdx.x * blockDim.x + threadIdx.x;
    if (idx >= NG * NDP) return;
    int k = idx / NDP, n = idx % NDP;
    g_Wp[idx] = (n < ND) ? W[k * ND + n] : 0.0f;
}

// deg starts at 1 (self loop weight 1), counts at 0
__global__ void k_init() {
    int i = blockIdx.x * blockDim.x + threadIdx.x;
    if (i < NN) { g_deg[i] = 1.0f; g_cnt[i] = 0; }
}

// degree (at target) and per-target edge counts
__global__ void k_degcnt(const void* __restrict__ ei,
                         const float* __restrict__ ew) {
    int e = blockIdx.x * blockDim.x + threadIdx.x;
    if (e >= NE) return;
    int c = edge_at(ei, NE + e);
    atomicAdd(&g_deg[c], ew[e]);
    atomicAdd(&g_cnt[c], 1);
}

// single-block scan of counts -> offsets; also dis = rsqrt(deg)
__global__ void k_scan() {
    __shared__ int part[1024];
    int t = threadIdx.x;
    int base = t * 10;
    int loc[10];
    int s = 0;
    #pragma unroll
    for (int j = 0; j < 10; j++) {
        int idx = base + j;
        int v = (idx < NN) ? g_cnt[idx] : 0;
        loc[j] = s; s += v;
    }
    part[t] = s;
    __syncthreads();
    for (int off = 1; off < 1024; off <<= 1) {
        int v = 0;
        if (t >= off) v = part[t - off];
        __syncthreads();
        if (t >= off) part[t] += v;
        __syncthreads();
    }
    int pre = (t > 0) ? part[t - 1] : 0;
    #pragma unroll
    for (int j = 0; j < 10; j++) {
        int idx = base + j;
        if (idx < NN) { int o = pre + loc[j]; g_off[idx] = o; g_cur[idx] = o; }
    }
    if (t == 1023) g_off[NN] = part[1023];
    for (int i = t; i < NN; i += 1024) g_dis[i] = rsqrtf(g_deg[i]);
}

// bin edges into CSR slots; precompute per-edge norm
__global__ void k_fill(const void* __restrict__ ei,
                       const float* __restrict__ ew) {
    int e = blockIdx.x * blockDim.x + threadIdx.x;
    if (e >= NE) return;
    int r = edge_at(ei, e);
    int c = edge_at(ei, NE + e);
    int slot = atomicAdd(&g_cur[c], 1);
    slot = slot < 0 ? 0 : (slot >= NE ? NE - 1 : slot);
    g_src[slot] = r;
    g_nrm[slot] = g_dis[r] * ew[e] * g_dis[c];
}

// GEMM: g_xw[10000,320] = x[10000,2000] @ g_Wp[2000,320]
// BM=128 BN=64 BK=16, 256 threads, 8x4 per thread, packed fma.rn.f32x2
__global__ void __launch_bounds__(256) k_gemm(const float* __restrict__ x) {
    const int bn = blockIdx.x * 64;
    const int gm = blockIdx.y * 128;
    const int tid = threadIdx.x;
    const int tx = tid & 15;
    const int ty = tid >> 4;
    const int my = ty * 8;    // 8 m rows (4 pairs)
    const int nx = tx * 4;    // 4 n cols

    __shared__ float As[16][128];  // transposed: As[k][m]
    __shared__ float Bs[16][64];   // Bs[k][n]

    unsigned long long acc[16];    // acc[p*4+n] = { c[m0][n], c[m1][n] }
    #pragma unroll
    for (int i = 0; i < 16; i++) acc[i] = 0ull;

    for (int kb = 0; kb < NG; kb += 16) {
        // x tile -> As (transposed). 512 float4 loads across 256 threads.
        #pragma unroll
        for (int g = 0; g < 2; g++) {
            int idx = tid + g * 256;        // 0..511
            int m   = idx >> 2;             // 0..127
            int kq  = (idx & 3) * 4;        // 0,4,8,12
            int row = gm + m;
            if (row > NN - 1) row = NN - 1; // clamp (stores guarded)
            float4 v = *(const float4*)(x + (size_t)row * NG + kb + kq);
            As[kq + 0][m] = v.x;
            As[kq + 1][m] = v.y;
            As[kq + 2][m] = v.z;
            As[kq + 3][m] = v.w;
        }
        // W tile -> Bs
        {
            int kk = tid >> 4;              // 0..15
            int n4 = (tid & 15) * 4;        // 0..60
            float4 v = *(const float4*)(g_Wp + (size_t)(kb + kk) * NDP + bn + n4);
            *(float4*)(&Bs[kk][n4]) = v;
        }
        __syncthreads();

        #pragma unroll
        for (int k = 0; k < 16; k++) {
            unsigned long long ap[4];
            #pragma unroll
            for (int p = 0; p < 4; p++)
                ap[p] = *(const unsigned long long*)(&As[k][my + 2 * p]);
            float4 bv = *(const float4*)(&Bs[k][nx]);
            unsigned long long bb[4];
            asm("mov.b64 %0, {%1,%1};" : "=l"(bb[0]) : "f"(bv.x));
            asm("mov.b64 %0, {%1,%1};" : "=l"(bb[1]) : "f"(bv.y));
            asm("mov.b64 %0, {%1,%1};" : "=l"(bb[2]) : "f"(bv.z));
            asm("mov.b64 %0, {%1,%1};" : "=l"(bb[3]) : "f"(bv.w));
            #pragma unroll
            for (int p = 0; p < 4; p++) {
                #pragma unroll
                for (int n = 0; n < 4; n++) {
                    asm("fma.rn.f32x2 %0, %1, %2, %0;"
                        : "+l"(acc[p * 4 + n])
                        : "l"(ap[p]), "l"(bb[n]));
                }
            }
        }
        __syncthreads();
    }

    // store
    #pragma unroll
    for (int p = 0; p < 4; p++) {
        float2 c0 = *(float2*)&acc[p * 4 + 0];
        float2 c1 = *(float2*)&acc[p * 4 + 1];
        float2 c2 = *(float2*)&acc[p * 4 + 2];
        float2 c3 = *(float2*)&acc[p * 4 + 3];
        int m0 = gm + my + 2 * p;
        if (m0 < NN) {
            float4 o = {c0.x, c1.x, c2.x, c3.x};
            *(float4*)(g_xw + (size_t)m0 * NDP + bn + nx) = o;
        }
        if (m0 + 1 < NN) {
            float4 o = {c0.y, c1.y, c2.y, c3.y};
            *(float4*)(g_xw + (size_t)(m0 + 1) * NDP + bn + nx) = o;
        }
    }
}

// fused: CSR aggregation + self-loop + bias + ReLU + embeddings + tiled output
// one block per node, 320 threads (one per padded channel)
__global__ void __launch_bounds__(320) k_agg_out(const float* __restrict__ b,
                                                 float* __restrict__ out) {
    __shared__ float sh[ND];
    const int n = blockIdx.x;
    const int c = threadIdx.x;   // 0..319 (pad cols of g_xw are zero)

    const float dn = g_dis[n];
    float acc = g_xw[(size_t)n * NDP + c] * (dn * dn);   // self loop

    const int p0 = g_off[n];
    const int p1 = g_off[n + 1];
    for (int p = p0; p < p1; ++p) {
        int   r  = g_src[p];
        float wn = g_nrm[p];
        acc += g_xw[(size_t)r * NDP + c] * wn;
    }

    if (c < ND) {
        float hv = fmaxf(acc + b[c], 0.0f);
        sh[c] = hv;
        __stcs(out + EMB_OFF + (size_t)n * ND + c, hv);
    }
    __syncthreads();

    float* op = out + (size_t)n * TILE_PER_NODE;
    for (int idx = c; idx < TILE_PER_NODE; idx += 320) {
        int cc = (idx / HDIM) % ND;
        __stcs(op + idx, sh[cc]);
    }
}

// ---------------- launch ----------------
extern "C" void kernel_launch(void* const* d_in, const int* in_sizes, int n_in,
                              void* d_out, int out_size) {
    const float* x  = (const float*)d_in[0];
    const void*  ei = d_in[1];                  // int32 or int64, detected on device
    const float* ew = (const float*)d_in[2];
    // d_in[3] = coordinate (unused by reference)
    const float* W  = (const float*)d_in[4];
    const float* b  = (const float*)d_in[5];
    float*       out = (float*)d_out;

    k_detect<<<1, 256>>>(ei);
    k_padW  <<<(NG * NDP + 255) / 256, 256>>>(W);
    k_init  <<<(NN + 255) / 256, 256>>>();
    k_degcnt<<<(NE + 255) / 256, 256>>>(ei, ew);
    k_scan  <<<1, 1024>>>();
    k_fill  <<<(NE + 255) / 256, 256>>>(ei, ew);
    k_gemm  <<<dim3(NDP / 64, (NN + 127) / 128), 256>>>(x);
    k_agg_out<<<NN, 320>>>(b, out);
}

// round 6
// speedup vs baseline: 1.4570x; 1.4570x over previous
#include <cuda_runtime.h>
#include <cuda_bf16.h>
#include <cstdint>

// ---------------- problem constants ----------------
#define NN      10000
#define NG      2000
#define ND      301
#define NDP     320        // padded embed dim
#define NE      320000
#define NHEADS  4
#define HDIM    12
#define TILE_PER_NODE (NHEADS * ND * HDIM)            // 14448
#define OUT_TILE_ELEMS ((size_t)NN * TILE_PER_NODE)   // 144,480,000
#define EMB_OFF OUT_TILE_ELEMS

#define KPAD    2048
#define BK      32
#define NKIT    (KPAD / BK)    // 64 k-iterations
#define BM      128
#define BN      64

// smem stage layout (bytes): rows padded to 40 bf16 (80 B) for ldmatrix
#define SROW    40
#define OFF_AHI 0
#define OFF_ALO 10240          // 128*40*2
#define OFF_BHI 20480
#define OFF_BLO 25600          // +64*40*2
#define STAGE_B 30720
#define GEMM_SMEM (2 * STAGE_B)  // 61440

// ---------------- device scratch ----------------
__device__ __nv_bfloat16 g_xhi[(size_t)NN * KPAD];
__device__ __nv_bfloat16 g_xlo[(size_t)NN * KPAD];
__device__ __nv_bfloat16 g_whi[(size_t)NDP * KPAD];   // W^T [n][k]
__device__ __nv_bfloat16 g_wlo[(size_t)NDP * KPAD];
__device__ float g_xw[(size_t)NN * NDP];
__device__ float g_deg[NN];
__device__ float g_dis[NN];
__device__ int   g_cnt[NN];
__device__ int   g_off[NN + 1];
__device__ int   g_cur[NN];
__device__ int   g_src[NE];
__device__ float g_nrm[NE];
__device__ int   g_is64;

// ---------------- small helpers ----------------
__device__ __forceinline__ uint32_t smem_u32(const void* p) {
    uint32_t a;
    asm("{ .reg .u64 t; cvta.to.shared.u64 t, %1; cvt.u32.u64 %0, t; }" : "=r"(a) : "l"(p));
    return a;
}
__device__ __forceinline__ void cp16(uint32_t saddr, const void* gaddr) {
    asm volatile("cp.async.cg.shared.global [%0], [%1], 16;" :: "r"(saddr), "l"(gaddr));
}
__device__ __forceinline__ void ldm_x4(uint32_t* r, uint32_t addr) {
    asm volatile("ldmatrix.sync.aligned.m8n8.x4.shared.b16 {%0,%1,%2,%3}, [%4];"
        : "=r"(r[0]), "=r"(r[1]), "=r"(r[2]), "=r"(r[3]) : "r"(addr));
}
__device__ __forceinline__ void mma_bf16(float* c, const uint32_t* a,
                                         uint32_t b0, uint32_t b1) {
    asm volatile("mma.sync.aligned.m16n8k16.row.col.f32.bf16.bf16.f32 "
        "{%0,%1,%2,%3}, {%4,%5,%6,%7}, {%8,%9}, {%0,%1,%2,%3};"
        : "+f"(c[0]), "+f"(c[1]), "+f"(c[2]), "+f"(c[3])
        : "r"(a[0]), "r"(a[1]), "r"(a[2]), "r"(a[3]), "r"(b0), "r"(b1));
}

// ---------------- edge-index dtype detection ----------------
__global__ void k_detect(const void* __restrict__ ei) {
    __shared__ int bad;
    if (threadIdx.x == 0) bad = 0;
    __syncthreads();
    const long long* p = (const long long*)ei;
    for (int i = threadIdx.x; i < 4096; i += blockDim.x) {
        long long v = p[i];
        if (v < 0 || v >= NN) bad = 1;
    }
    __syncthreads();
    if (threadIdx.x == 0) g_is64 = bad ? 0 : 1;
}
__device__ __forceinline__ int edge_at(const void* __restrict__ ei, int pos) {
    int v = g_is64 ? (int)((const long long*)ei)[pos] : ((const int*)ei)[pos];
    return v < 0 ? 0 : (v >= NN ? NN - 1 : v);
}

// ---------------- CSR build ----------------
__global__ void k_init() {
    int i = blockIdx.x * blockDim.x + threadIdx.x;
    if (i < NN) { g_deg[i] = 1.0f; g_cnt[i] = 0; }
}
__global__ void k_degcnt(const void* __restrict__ ei, const float* __restrict__ ew) {
    int e = blockIdx.x * blockDim.x + threadIdx.x;
    if (e >= NE) return;
    int c = edge_at(ei, NE + e);
    atomicAdd(&g_deg[c], ew[e]);
    atomicAdd(&g_cnt[c], 1);
}
__global__ void k_scan() {
    __shared__ int part[1024];
    int t = threadIdx.x;
    int base = t * 10;
    int loc[10];
    int s = 0;
    #pragma unroll
    for (int j = 0; j < 10; j++) {
        int idx = base + j;
        int v = (idx < NN) ? g_cnt[idx] : 0;
        loc[j] = s; s += v;
    }
    part[t] = s;
    __syncthreads();
    for (int off = 1; off < 1024; off <<= 1) {
        int v = 0;
        if (t >= off) v = part[t - off];
        __syncthreads();
        if (t >= off) part[t] += v;
        __syncthreads();
    }
    int pre = (t > 0) ? part[t - 1] : 0;
    #pragma unroll
    for (int j = 0; j < 10; j++) {
        int idx = base + j;
        if (idx < NN) { int o = pre + loc[j]; g_off[idx] = o; g_cur[idx] = o; }
    }
    if (t == 1023) g_off[NN] = part[1023];
    for (int i = t; i < NN; i += 1024) g_dis[i] = rsqrtf(g_deg[i]);
}
__global__ void k_fill(const void* __restrict__ ei, const float* __restrict__ ew) {
    int e = blockIdx.x * blockDim.x + threadIdx.x;
    if (e >= NE) return;
    int r = edge_at(ei, e);
    int c = edge_at(ei, NE + e);
    int slot = atomicAdd(&g_cur[c], 1);
    slot = slot < 0 ? 0 : (slot >= NE ? NE - 1 : slot);
    g_src[slot] = r;
    g_nrm[slot] = g_dis[r] * ew[e] * g_dis[c];
}

// ---------------- fp32 -> bf16 hi/lo split ----------------
__global__ void __launch_bounds__(256) k_convx(const float* __restrict__ x) {
    int row = blockIdx.x;
    int col = threadIdx.x * 8;
    float a[8];
    if (col + 8 <= NG) {
        const float4* p = (const float4*)(x + (size_t)row * NG + col);
        float4 v0 = p[0], v1 = p[1];
        a[0] = v0.x; a[1] = v0.y; a[2] = v0.z; a[3] = v0.w;
        a[4] = v1.x; a[5] = v1.y; a[6] = v1.z; a[7] = v1.w;
    } else {
        #pragma unroll
        for (int j = 0; j < 8; j++)
            a[j] = (col + j < NG) ? x[(size_t)row * NG + col + j] : 0.0f;
    }
    unsigned short hi[8], lo[8];
    #pragma unroll
    for (int j = 0; j < 8; j++) {
        __nv_bfloat16 h = __float2bfloat16_rn(a[j]);
        __nv_bfloat16 l = __float2bfloat16_rn(a[j] - __bfloat162float(h));
        hi[j] = *(unsigned short*)&h;
        lo[j] = *(unsigned short*)&l;
    }
    *(uint4*)(&g_xhi[(size_t)row * KPAD + col]) = *(uint4*)hi;
    *(uint4*)(&g_xlo[(size_t)row * KPAD + col]) = *(uint4*)lo;
}
__global__ void __launch_bounds__(256) k_convw(const float* __restrict__ W) {
    int n = blockIdx.x;   // 0..319
    for (int k = threadIdx.x; k < KPAD; k += 256) {
        float v = (n < ND && k < NG) ? W[(size_t)k * ND + n] : 0.0f;
        __nv_bfloat16 h = __float2bfloat16_rn(v);
        __nv_bfloat16 l = __float2bfloat16_rn(v - __bfloat162float(h));
        g_whi[(size_t)n * KPAD + k] = h;
        g_wlo[(size_t)n * KPAD + k] = l;
    }
}

// ---------------- mma.sync bf16 GEMM with hi/lo split ----------------
// D = Ahi*Bhi + Alo*Bhi + Ahi*Blo   (single fp32 accumulator set)
// BM=128 BN=64 BK=32, 8 warps (warp tile 32x32), 2-stage cp.async pipeline.
__device__ __forceinline__ void load_stage(uint32_t sbase, int gm, int bn, int kb, int tid) {
    // A: 128 rows x 32 bf16 (hi & lo), 512 x 16B transfers each
    #pragma unroll
    for (int g = 0; g < 2; g++) {
        int idx = tid + g * 256;
        int row = idx >> 2, q = idx & 3;
        int gr = gm + row; if (gr >= NN) gr = NN - 1;
        size_t go = (size_t)gr * KPAD + kb + q * 8;
        uint32_t so = (row * SROW + q * 8) * 2;
        cp16(sbase + OFF_AHI + so, &g_xhi[go]);
        cp16(sbase + OFF_ALO + so, &g_xlo[go]);
    }
    // B: 64 rows x 32 bf16 (hi & lo), 256 x 16B each
    {
        int row = tid >> 2, q = tid & 3;
        size_t go = (size_t)(bn + row) * KPAD + kb + q * 8;
        uint32_t so = (row * SROW + q * 8) * 2;
        cp16(sbase + OFF_BHI + so, &g_whi[go]);
        cp16(sbase + OFF_BLO + so, &g_wlo[go]);
    }
}

__global__ void __launch_bounds__(256) k_gemm(int dummy) {
    extern __shared__ char smem[];
    const uint32_t sb = smem_u32(smem);
    const int tid  = threadIdx.x;
    const int lane = tid & 31;
    const int wid  = tid >> 5;
    const int wm   = (wid & 3) * 32;       // warp M offset in tile
    const int wn   = (wid >> 2) * 32;      // warp N offset in tile
    const int gm   = blockIdx.x * BM;
    const int bn   = blockIdx.y * BN;

    // ldmatrix lane-address components
    const int a_row  = wm + (lane & 7) + ((lane >> 3) & 1) * 8;
    const int a_colb = (lane >> 4) * 8;
    const int b_row  = wn + (lane & 7) + ((lane >> 4) << 3);
    const int b_colb = ((lane >> 3) & 1) * 8;

    float acc[2][4][4];
    #pragma unroll
    for (int i = 0; i < 2; i++)
        #pragma unroll
        for (int j = 0; j < 4; j++)
            #pragma unroll
            for (int q = 0; q < 4; q++) acc[i][j][q] = 0.0f;

    // prologue: fill both stages
    load_stage(sb, gm, bn, 0, tid);
    asm volatile("cp.async.commit_group;" ::: "memory");
    load_stage(sb + STAGE_B, gm, bn, BK, tid);
    asm volatile("cp.async.commit_group;" ::: "memory");

    for (int c = 0; c < NKIT; ++c) {
        asm volatile("cp.async.wait_group 1;" ::: "memory");
        __syncthreads();

        const uint32_t st = sb + (c & 1) * STAGE_B;
        #pragma unroll
        for (int ks = 0; ks < 2; ++ks) {
            uint32_t aH[2][4], aL[2][4], bH[2][4], bL[2][4];
            #pragma unroll
            for (int mt = 0; mt < 2; ++mt) {
                uint32_t ao = ((a_row + mt * 16) * SROW + ks * 16 + a_colb) * 2;
                ldm_x4(aH[mt], st + OFF_AHI + ao);
                ldm_x4(aL[mt], st + OFF_ALO + ao);
            }
            #pragma unroll
            for (int ng = 0; ng < 2; ++ng) {
                uint32_t bo = ((b_row + ng * 16) * SROW + ks * 16 + b_colb) * 2;
                ldm_x4(bH[ng], st + OFF_BHI + bo);
                ldm_x4(bL[ng], st + OFF_BLO + bo);
            }
            #pragma unroll
            for (int mt = 0; mt < 2; ++mt) {
                #pragma unroll
                for (int j = 0; j < 4; ++j) {
                    int g = j >> 1, p = (j & 1) * 2;
                    mma_bf16(acc[mt][j], aH[mt], bH[g][p], bH[g][p + 1]);
                    mma_bf16(acc[mt][j], aL[mt], bH[g][p], bH[g][p + 1]);
                    mma_bf16(acc[mt][j], aH[mt], bL[g][p], bL[g][p + 1]);
                }
            }
        }
        __syncthreads();

        if (c + 2 < NKIT)
            load_stage(sb + (c & 1) * STAGE_B, gm, bn, (c + 2) * BK, tid);
        asm volatile("cp.async.commit_group;" ::: "memory");
    }

    // epilogue: fragment -> g_xw
    const int gid = lane >> 2, tig = lane & 3;
    #pragma unroll
    for (int mt = 0; mt < 2; ++mt) {
        int r0 = gm + wm + mt * 16 + gid;
        #pragma unroll
        for (int j = 0; j < 4; ++j) {
            int col = bn + wn + j * 8 + tig * 2;
            if (r0 < NN)
                *(float2*)(g_xw + (size_t)r0 * NDP + col) =
                    make_float2(acc[mt][j][0], acc[mt][j][1]);
            if (r0 + 8 < NN)
                *(float2*)(g_xw + (size_t)(r0 + 8) * NDP + col) =
                    make_float2(acc[mt][j][2], acc[mt][j][3]);
        }
    }
}

// ---------------- aggregation (writes embeddings) ----------------
__global__ void __launch_bounds__(320) k_agg(const float* __restrict__ b,
                                             float* __restrict__ out) {
    const int n = blockIdx.x;
    const int c = threadIdx.x;
    const float dn = g_dis[n];
    float acc = g_xw[(size_t)n * NDP + c] * (dn * dn);
    const int p0 = g_off[n], p1 = g_off[n + 1];
    for (int p = p0; p < p1; ++p)
        acc += g_xw[(size_t)g_src[p] * NDP + c] * g_nrm[p];
    if (c < ND)
        out[EMB_OFF + (size_t)n * ND + c] = fmaxf(acc + b[c], 0.0f);
}

// ---------------- tiled broadcast: 3612 splat float4 per node ----------------
__global__ void __launch_bounds__(256) k_bcast(const float* __restrict__ out_emb,
                                               float* __restrict__ out) {
    __shared__ float sh[ND];
    const int n = blockIdx.x;
    for (int i = threadIdx.x; i < ND; i += 256)
        sh[i] = out_emb[(size_t)n * ND + i];
    __syncthreads();
    float4* op = (float4*)(out + (size_t)n * TILE_PER_NODE);
    for (int i = threadIdx.x; i < TILE_PER_NODE / 4; i += 256) {
        int g = i / 3;          // (h*301 + c)
        int c = g % ND;
        float v = sh[c];
        float4 f = {v, v, v, v};
        __stcs(op + i, f);
    }
}

// ---------------- launch ----------------
extern "C" void kernel_launch(void* const* d_in, const int* in_sizes, int n_in,
                              void* d_out, int out_size) {
    const float* x  = (const float*)d_in[0];
    const void*  ei = d_in[1];
    const float* ew = (const float*)d_in[2];
    const float* W  = (const float*)d_in[4];
    const float* b  = (const float*)d_in[5];
    float*       out = (float*)d_out;

    static int smem_set = 0;
    if (!smem_set) {
        cudaFuncSetAttribute(k_gemm, cudaFuncAttributeMaxDynamicSharedMemorySize, GEMM_SMEM);
        smem_set = 1;
    }

    k_detect<<<1, 256>>>(ei);
    k_init  <<<(NN + 255) / 256, 256>>>();
    k_degcnt<<<(NE + 255) / 256, 256>>>(ei, ew);
    k_scan  <<<1, 1024>>>();
    k_fill  <<<(NE + 255) / 256, 256>>>(ei, ew);
    k_convx <<<NN, 256>>>(x);
    k_convw <<<NDP, 256>>>(W);
    k_gemm  <<<dim3((NN + BM - 1) / BM, NDP / BN), 256, GEMM_SMEM>>>(0);
    k_agg   <<<NN, 320>>>(b, out);
    k_bcast <<<NN, 256>>>(out + EMB_OFF, out);
}

// round 7
// speedup vs baseline: 2.0029x; 1.3747x over previous
#include <cuda_runtime.h>
#include <cuda_fp16.h>
#include <cstdint>

// ---------------- problem constants ----------------
#define NN      10000
#define NG      2000
#define ND      301
#define NDP     320        // padded embed dim
#define NE      320000
#define NHEADS  4
#define HDIM    12
#define TILE_PER_NODE (NHEADS * ND * HDIM)            // 14448
#define OUT_TILE_ELEMS ((size_t)NN * TILE_PER_NODE)   // 144,480,000
#define EMB_OFF OUT_TILE_ELEMS

#define KPAD    2048
#define BK      32
#define NKIT    (KPAD / BK)    // 64
#define BM      128
#define BN      64
#define NSTAGE  4

// smem stage layout: rows padded to 40 fp16 (80 B) for conflict-free ldmatrix
#define SROW    40
#define OFF_A   0
#define OFF_B   10240          // 128*40*2
#define STAGE_B 15360          // + 64*40*2
#define GEMM_SMEM (NSTAGE * STAGE_B)   // 61440

// ---------------- device scratch ----------------
__device__ __half g_xh[(size_t)NN * KPAD];    // 41 MB
__device__ __half g_wh[(size_t)NDP * KPAD];   // W^T [n][k]
__device__ float g_xw[(size_t)NN * NDP];
__device__ float g_deg[NN];
__device__ float g_dis[NN];
__device__ int   g_cnt[NN];
__device__ int   g_off[NN + 1];
__device__ int   g_cur[NN];
__device__ int   g_src[NE];
__device__ float g_nrm[NE];
__device__ int   g_is64;

// ---------------- small helpers ----------------
__device__ __forceinline__ uint32_t smem_u32(const void* p) {
    uint32_t a;
    asm("{ .reg .u64 t; cvta.to.shared.u64 t, %1; cvt.u32.u64 %0, t; }" : "=r"(a) : "l"(p));
    return a;
}
__device__ __forceinline__ void cp16(uint32_t saddr, const void* gaddr) {
    asm volatile("cp.async.cg.shared.global [%0], [%1], 16;" :: "r"(saddr), "l"(gaddr));
}
__device__ __forceinline__ void ldm_x4(uint32_t* r, uint32_t addr) {
    asm volatile("ldmatrix.sync.aligned.m8n8.x4.shared.b16 {%0,%1,%2,%3}, [%4];"
        : "=r"(r[0]), "=r"(r[1]), "=r"(r[2]), "=r"(r[3]) : "r"(addr));
}
__device__ __forceinline__ void mma_fp16(float* c, const uint32_t* a,
                                         uint32_t b0, uint32_t b1) {
    asm volatile("mma.sync.aligned.m16n8k16.row.col.f32.f16.f16.f32 "
        "{%0,%1,%2,%3}, {%4,%5,%6,%7}, {%8,%9}, {%0,%1,%2,%3};"
        : "+f"(c[0]), "+f"(c[1]), "+f"(c[2]), "+f"(c[3])
        : "r"(a[0]), "r"(a[1]), "r"(a[2]), "r"(a[3]), "r"(b0), "r"(b1));
}

// ---------------- edge-index dtype + init (merged) ----------------
__global__ void k_detect_init(const void* __restrict__ ei) {
    __shared__ int bad;
    int i = blockIdx.x * blockDim.x + threadIdx.x;
    if (i < NN) { g_deg[i] = 1.0f; g_cnt[i] = 0; }
    if (blockIdx.x == 0) {
        if (threadIdx.x == 0) bad = 0;
        __syncthreads();
        const long long* p = (const long long*)ei;
        for (int k = threadIdx.x; k < 4096; k += blockDim.x) {
            long long v = p[k];
            if (v < 0 || v >= NN) bad = 1;
        }
        __syncthreads();
        if (threadIdx.x == 0) g_is64 = bad ? 0 : 1;
    }
}
__device__ __forceinline__ int edge_at(const void* __restrict__ ei, int pos) {
    int v = g_is64 ? (int)((const long long*)ei)[pos] : ((const int*)ei)[pos];
    return v < 0 ? 0 : (v >= NN ? NN - 1 : v);
}

// ---------------- CSR build ----------------
__global__ void k_degcnt(const void* __restrict__ ei, const float* __restrict__ ew) {
    int e = blockIdx.x * blockDim.x + threadIdx.x;
    if (e >= NE) return;
    int c = edge_at(ei, NE + e);
    atomicAdd(&g_deg[c], ew[e]);
    atomicAdd(&g_cnt[c], 1);
}

// shfl-based single-block scan (2 barriers) + dis = rsqrt(deg)
__global__ void k_scan() {
    __shared__ int wsum[32];
    const int t = threadIdx.x;          // 0..1023
    const int lane = t & 31, warp = t >> 5;
    const int base = t * 10;
    int loc[10];
    int s = 0;
    #pragma unroll
    for (int j = 0; j < 10; j++) {
        int idx = base + j;
        int v = (idx < NN) ? g_cnt[idx] : 0;
        loc[j] = s; s += v;
    }
    int inc = s;
    #pragma unroll
    for (int o = 1; o < 32; o <<= 1) {
        int n = __shfl_up_sync(0xFFFFFFFF, inc, o);
        if (lane >= o) inc += n;
    }
    if (lane == 31) wsum[warp] = inc;
    __syncthreads();
    if (warp == 0) {
        int w = wsum[lane];
        #pragma unroll
        for (int o = 1; o < 32; o <<= 1) {
            int n = __shfl_up_sync(0xFFFFFFFF, w, o);
            if (lane >= o) w += n;
        }
        wsum[lane] = w;
    }
    __syncthreads();
    int pre = inc - s + (warp ? wsum[warp - 1] : 0);
    #pragma unroll
    for (int j = 0; j < 10; j++) {
        int idx = base + j;
        if (idx < NN) { int o = pre + loc[j]; g_off[idx] = o; g_cur[idx] = o; }
    }
    if (t == 1023) g_off[NN] = wsum[31];
    #pragma unroll
    for (int r = 0; r < 10; r++) {
        int i = t + r * 1024;
        if (i < NN) g_dis[i] = rsqrtf(g_deg[i]);
    }
}
__global__ void k_fill(const void* __restrict__ ei, const float* __restrict__ ew) {
    int e = blockIdx.x * blockDim.x + threadIdx.x;
    if (e >= NE) return;
    int r = edge_at(ei, e);
    int c = edge_at(ei, NE + e);
    int slot = atomicAdd(&g_cur[c], 1);
    slot = slot < 0 ? 0 : (slot >= NE ? NE - 1 : slot);
    g_src[slot] = r;
    g_nrm[slot] = g_dis[r] * ew[e] * g_dis[c];
}

// ---------------- fp32 -> fp16 conversion ----------------
__global__ void __launch_bounds__(256) k_convx(const float* __restrict__ x) {
    int row = blockIdx.x;
    int col = threadIdx.x * 8;
    float a[8];
    if (col + 8 <= NG) {
        const float4* p = (const float4*)(x + (size_t)row * NG + col);
        float4 v0 = p[0], v1 = p[1];
        a[0] = v0.x; a[1] = v0.y; a[2] = v0.z; a[3] = v0.w;
        a[4] = v1.x; a[5] = v1.y; a[6] = v1.z; a[7] = v1.w;
    } else {
        #pragma unroll
        for (int j = 0; j < 8; j++)
            a[j] = (col + j < NG) ? x[(size_t)row * NG + col + j] : 0.0f;
    }
    unsigned short h[8];
    #pragma unroll
    for (int j = 0; j < 8; j++) {
        __half v = __float2half_rn(a[j]);
        h[j] = *(unsigned short*)&v;
    }
    *(uint4*)(&g_xh[(size_t)row * KPAD + col]) = *(uint4*)h;
}
__global__ void __launch_bounds__(256) k_convw(const float* __restrict__ W) {
    int n = blockIdx.x;   // 0..319
    for (int k = threadIdx.x; k < KPAD; k += 256) {
        float v = (n < ND && k < NG) ? W[(size_t)k * ND + n] : 0.0f;
        g_wh[(size_t)n * KPAD + k] = __float2half_rn(v);
    }
}

// ---------------- mma.sync fp16 GEMM, 4-stage cp.async pipeline ----------------
__device__ __forceinline__ void load_stage(uint32_t sbase, int gm, int bn, int kb, int tid) {
    // A: 128 rows x 32 fp16, 512 x 16B transfers
    #pragma unroll
    for (int g = 0; g < 2; g++) {
        int idx = tid + g * 256;
        int row = idx >> 2, q = idx & 3;
        int gr = gm + row; if (gr >= NN) gr = NN - 1;
        cp16(sbase + OFF_A + (row * SROW + q * 8) * 2,
             &g_xh[(size_t)gr * KPAD + kb + q * 8]);
    }
    // B: 64 rows x 32 fp16, 256 x 16B
    {
        int row = tid >> 2, q = tid & 3;
        cp16(sbase + OFF_B + (row * SROW + q * 8) * 2,
             &g_wh[(size_t)(bn + row) * KPAD + kb + q * 8]);
    }
}

__global__ void __launch_bounds__(256) k_gemm(int dummy) {
    extern __shared__ char smem[];
    const uint32_t sb = smem_u32(smem);
    const int tid  = threadIdx.x;
    const int lane = tid & 31;
    const int wid  = tid >> 5;
    const int wm   = (wid & 3) * 32;
    const int wn   = (wid >> 2) * 32;
    const int gm   = blockIdx.x * BM;
    const int bn   = blockIdx.y * BN;

    const int a_row  = wm + (lane & 7) + ((lane >> 3) & 1) * 8;
    const int a_colb = (lane >> 4) * 8;
    const int b_row  = wn + (lane & 7) + ((lane >> 4) << 3);
    const int b_colb = ((lane >> 3) & 1) * 8;

    float acc[2][4][4];
    #pragma unroll
    for (int i = 0; i < 2; i++)
        #pragma unroll
        for (int j = 0; j < 4; j++)
            #pragma unroll
            for (int q = 0; q < 4; q++) acc[i][j][q] = 0.0f;

    // prologue: fill 3 of 4 stages
    #pragma unroll
    for (int s = 0; s < NSTAGE - 1; s++) {
        load_stage(sb + s * STAGE_B, gm, bn, s * BK, tid);
        asm volatile("cp.async.commit_group;" ::: "memory");
    }

    for (int c = 0; c < NKIT; ++c) {
        asm volatile("cp.async.wait_group %0;" :: "n"(NSTAGE - 2) : "memory");
        __syncthreads();

        // issue next stage's loads first (targets buffer finished at iter c-1)
        if (c + NSTAGE - 1 < NKIT)
            load_stage(sb + ((c + NSTAGE - 1) & (NSTAGE - 1)) * STAGE_B,
                       gm, bn, (c + NSTAGE - 1) * BK, tid);
        asm volatile("cp.async.commit_group;" ::: "memory");

        const uint32_t st = sb + (c & (NSTAGE - 1)) * STAGE_B;
        #pragma unroll
        for (int ks = 0; ks < 2; ++ks) {
            uint32_t aF[2][4], bF[2][4];
            #pragma unroll
            for (int mt = 0; mt < 2; ++mt)
                ldm_x4(aF[mt], st + OFF_A + ((a_row + mt * 16) * SROW + ks * 16 + a_colb) * 2);
            #pragma unroll
            for (int ng = 0; ng < 2; ++ng)
                ldm_x4(bF[ng], st + OFF_B + ((b_row + ng * 16) * SROW + ks * 16 + b_colb) * 2);
            #pragma unroll
            for (int mt = 0; mt < 2; ++mt) {
                #pragma unroll
                for (int j = 0; j < 4; ++j) {
                    int g = j >> 1, p = (j & 1) * 2;
                    mma_fp16(acc[mt][j], aF[mt], bF[g][p], bF[g][p + 1]);
                }
            }
        }
        __syncthreads();
    }

    // epilogue: fragment -> g_xw
    const int gid = lane >> 2, tig = lane & 3;
    #pragma unroll
    for (int mt = 0; mt < 2; ++mt) {
        int r0 = gm + wm + mt * 16 + gid;
        #pragma unroll
        for (int j = 0; j < 4; ++j) {
            int col = bn + wn + j * 8 + tig * 2;
            if (r0 < NN)
                *(float2*)(g_xw + (size_t)r0 * NDP + col) =
                    make_float2(acc[mt][j][0], acc[mt][j][1]);
            if (r0 + 8 < NN)
                *(float2*)(g_xw + (size_t)(r0 + 8) * NDP + col) =
                    make_float2(acc[mt][j][2], acc[mt][j][3]);
        }
    }
}

// ---------------- aggregation (writes embeddings) ----------------
__global__ void __launch_bounds__(320) k_agg(const float* __restrict__ b,
                                             float* __restrict__ out) {
    const int n = blockIdx.x;
    const int c = threadIdx.x;
    const float dn = g_dis[n];
    float acc = g_xw[(size_t)n * NDP + c] * (dn * dn);
    const int p0 = g_off[n], p1 = g_off[n + 1];
    for (int p = p0; p < p1; ++p)
        acc += g_xw[(size_t)g_src[p] * NDP + c] * g_nrm[p];
    if (c < ND)
        out[EMB_OFF + (size_t)n * ND + c] = fmaxf(acc + b[c], 0.0f);
}

// ---------------- tiled broadcast: splat float4 ----------------
__global__ void __launch_bounds__(256) k_bcast(const float* __restrict__ out_emb,
                                               float* __restrict__ out) {
    __shared__ float sh[ND];
    const int n = blockIdx.x;
    for (int i = threadIdx.x; i < ND; i += 256)
        sh[i] = out_emb[(size_t)n * ND + i];
    __syncthreads();
    float4* op = (float4*)(out + (size_t)n * TILE_PER_NODE);
    for (int i = threadIdx.x; i < TILE_PER_NODE / 4; i += 256) {
        int g = i / 3;          // (h*301 + c)
        int c = g % ND;
        float v = sh[c];
        float4 f = {v, v, v, v};
        __stcs(op + i, f);
    }
}

// ---------------- launch ----------------
extern "C" void kernel_launch(void* const* d_in, const int* in_sizes, int n_in,
                              void* d_out, int out_size) {
    const float* x  = (const float*)d_in[0];
    const void*  ei = d_in[1];
    const float* ew = (const float*)d_in[2];
    const float* W  = (const float*)d_in[4];
    const float* b  = (const float*)d_in[5];
    float*       out = (float*)d_out;

    static int smem_set = 0;
    if (!smem_set) {
        cudaFuncSetAttribute(k_gemm, cudaFuncAttributeMaxDynamicSharedMemorySize, GEMM_SMEM);
        smem_set = 1;
    }

    k_detect_init<<<(NN + 255) / 256, 256>>>(ei);
    k_degcnt<<<(NE + 255) / 256, 256>>>(ei, ew);
    k_scan  <<<1, 1024>>>();
    k_fill  <<<(NE + 255) / 256, 256>>>(ei, ew);
    k_convx <<<NN, 256>>>(x);
    k_convw <<<NDP, 256>>>(W);
    k_gemm  <<<dim3((NN + BM - 1) / BM, NDP / BN), 256, GEMM_SMEM>>>(0);
    k_agg   <<<NN, 320>>>(b, out);
    k_bcast <<<NN, 256>>>(out + EMB_OFF, out);
}

// round 8
// speedup vs baseline: 2.5922x; 1.2943x over previous
#include <cuda_runtime.h>
#include <cuda_fp16.h>
#include <cstdint>

// ---------------- problem constants ----------------
#define NN      10000
#define NG      2000
#define ND      301
#define NDP     320        // padded embed dim
#define NE      320000
#define NHEADS  4
#define HDIM    12
#define TILE_PER_NODE (NHEADS * ND * HDIM)            // 14448
#define OUT_TILE_ELEMS ((size_t)NN * TILE_PER_NODE)   // 144,480,000
#define EMB_OFF OUT_TILE_ELEMS

#define KPAD    2048
#define BK      32
#define NKIT    (KPAD / BK)    // 64
#define BM      128
#define BN      64
#define NSTAGE  4

// smem stage layout: rows padded to 40 fp16 (80 B) for conflict-free ldmatrix
#define SROW    40
#define OFF_A   0
#define OFF_B   10240          // 128*40*2
#define STAGE_B 15360          // + 64*40*2
#define GEMM_SMEM (NSTAGE * STAGE_B)   // 61440

// ---------------- device scratch ----------------
__device__ __half g_xh[(size_t)NN * KPAD];    // 41 MB
__device__ __half g_wh[(size_t)NDP * KPAD];   // W^T [n][k]
__device__ float g_xw[(size_t)NN * NDP];
__device__ float g_deg[NN];
__device__ float g_dis[NN];
__device__ int   g_cnt[NN];
__device__ int   g_off[NN + 1];
__device__ int   g_cur[NN];
__device__ int   g_src[NE];
__device__ float g_nrm[NE];
__device__ int   g_is64;

// ---------------- small helpers ----------------
__device__ __forceinline__ uint32_t smem_u32(const void* p) {
    uint32_t a;
    asm("{ .reg .u64 t; cvta.to.shared.u64 t, %1; cvt.u32.u64 %0, t; }" : "=r"(a) : "l"(p));
    return a;
}
__device__ __forceinline__ void cp16(uint32_t saddr, const void* gaddr) {
    asm volatile("cp.async.cg.shared.global [%0], [%1], 16;" :: "r"(saddr), "l"(gaddr));
}
__device__ __forceinline__ void ldm_x4(uint32_t* r, uint32_t addr) {
    asm volatile("ldmatrix.sync.aligned.m8n8.x4.shared.b16 {%0,%1,%2,%3}, [%4];"
        : "=r"(r[0]), "=r"(r[1]), "=r"(r[2]), "=r"(r[3]) : "r"(addr));
}
__device__ __forceinline__ void mma_fp16(float* c, const uint32_t* a,
                                         uint32_t b0, uint32_t b1) {
    asm volatile("mma.sync.aligned.m16n8k16.row.col.f32.f16.f16.f32 "
        "{%0,%1,%2,%3}, {%4,%5,%6,%7}, {%8,%9}, {%0,%1,%2,%3};"
        : "+f"(c[0]), "+f"(c[1]), "+f"(c[2]), "+f"(c[3])
        : "r"(a[0]), "r"(a[1]), "r"(a[2]), "r"(a[3]), "r"(b0), "r"(b1));
}

// ---------------- edge-index dtype + init (merged) ----------------
__global__ void k_detect_init(const void* __restrict__ ei) {
    __shared__ int bad;
    int i = blockIdx.x * blockDim.x + threadIdx.x;
    if (i < NN) { g_deg[i] = 1.0f; g_cnt[i] = 0; }
    if (blockIdx.x == 0) {
        if (threadIdx.x == 0) bad = 0;
        __syncthreads();
        const long long* p = (const long long*)ei;
        for (int k = threadIdx.x; k < 4096; k += blockDim.x) {
            long long v = p[k];
            if (v < 0 || v >= NN) bad = 1;
        }
        __syncthreads();
        if (threadIdx.x == 0) g_is64 = bad ? 0 : 1;
    }
}
__device__ __forceinline__ int edge_at(const void* __restrict__ ei, int pos) {
    int v = g_is64 ? (int)((const long long*)ei)[pos] : ((const int*)ei)[pos];
    return v < 0 ? 0 : (v >= NN ? NN - 1 : v);
}

// ---------------- CSR build ----------------
__global__ void k_degcnt(const void* __restrict__ ei, const float* __restrict__ ew) {
    int e = blockIdx.x * blockDim.x + threadIdx.x;
    if (e >= NE) return;
    int c = edge_at(ei, NE + e);
    atomicAdd(&g_deg[c], ew[e]);
    atomicAdd(&g_cnt[c], 1);
}

// shfl-based single-block scan (2 barriers) + dis = rsqrt(deg)
__global__ void k_scan() {
    __shared__ int wsum[32];
    const int t = threadIdx.x;          // 0..1023
    const int lane = t & 31, warp = t >> 5;
    const int base = t * 10;
    int loc[10];
    int s = 0;
    #pragma unroll
    for (int j = 0; j < 10; j++) {
        int idx = base + j;
        int v = (idx < NN) ? g_cnt[idx] : 0;
        loc[j] = s; s += v;
    }
    int inc = s;
    #pragma unroll
    for (int o = 1; o < 32; o <<= 1) {
        int n = __shfl_up_sync(0xFFFFFFFF, inc, o);
        if (lane >= o) inc += n;
    }
    if (lane == 31) wsum[warp] = inc;
    __syncthreads();
    if (warp == 0) {
        int w = wsum[lane];
        #pragma unroll
        for (int o = 1; o < 32; o <<= 1) {
            int n = __shfl_up_sync(0xFFFFFFFF, w, o);
            if (lane >= o) w += n;
        }
        wsum[lane] = w;
    }
    __syncthreads();
    int pre = inc - s + (warp ? wsum[warp - 1] : 0);
    #pragma unroll
    for (int j = 0; j < 10; j++) {
        int idx = base + j;
        if (idx < NN) { int o = pre + loc[j]; g_off[idx] = o; g_cur[idx] = o; }
    }
    if (t == 1023) g_off[NN] = wsum[31];
    #pragma unroll
    for (int r = 0; r < 10; r++) {
        int i = t + r * 1024;
        if (i < NN) g_dis[i] = rsqrtf(g_deg[i]);
    }
}
__global__ void k_fill(const void* __restrict__ ei, const float* __restrict__ ew) {
    int e = blockIdx.x * blockDim.x + threadIdx.x;
    if (e >= NE) return;
    int r = edge_at(ei, e);
    int c = edge_at(ei, NE + e);
    int slot = atomicAdd(&g_cur[c], 1);
    slot = slot < 0 ? 0 : (slot >= NE ? NE - 1 : slot);
    g_src[slot] = r;
    g_nrm[slot] = g_dis[r] * ew[e] * g_dis[c];
}

// ---------------- fp32 -> fp16 conversion ----------------
__global__ void __launch_bounds__(256) k_convx(const float* __restrict__ x) {
    int row = blockIdx.x;
    int col = threadIdx.x * 8;
    float a[8];
    if (col + 8 <= NG) {
        const float4* p = (const float4*)(x + (size_t)row * NG + col);
        float4 v0 = p[0], v1 = p[1];
        a[0] = v0.x; a[1] = v0.y; a[2] = v0.z; a[3] = v0.w;
        a[4] = v1.x; a[5] = v1.y; a[6] = v1.z; a[7] = v1.w;
    } else {
        #pragma unroll
        for (int j = 0; j < 8; j++)
            a[j] = (col + j < NG) ? x[(size_t)row * NG + col + j] : 0.0f;
    }
    unsigned short h[8];
    #pragma unroll
    for (int j = 0; j < 8; j++) {
        __half v = __float2half_rn(a[j]);
        h[j] = *(unsigned short*)&v;
    }
    *(uint4*)(&g_xh[(size_t)row * KPAD + col]) = *(uint4*)h;
}
__global__ void __launch_bounds__(256) k_convw(const float* __restrict__ W) {
    int n = blockIdx.x;   // 0..319
    for (int k = threadIdx.x; k < KPAD; k += 256) {
        float v = (n < ND && k < NG) ? W[(size_t)k * ND + n] : 0.0f;
        g_wh[(size_t)n * KPAD + k] = __float2half_rn(v);
    }
}

// ---------------- mma.sync fp16 GEMM, 4-stage cp.async pipeline ----------------
__device__ __forceinline__ void load_stage(uint32_t sbase, int gm, int bn, int kb, int tid) {
    #pragma unroll
    for (int g = 0; g < 2; g++) {
        int idx = tid + g * 256;
        int row = idx >> 2, q = idx & 3;
        int gr = gm + row; if (gr >= NN) gr = NN - 1;
        cp16(sbase + OFF_A + (row * SROW + q * 8) * 2,
             &g_xh[(size_t)gr * KPAD + kb + q * 8]);
    }
    {
        int row = tid >> 2, q = tid & 3;
        cp16(sbase + OFF_B + (row * SROW + q * 8) * 2,
             &g_wh[(size_t)(bn + row) * KPAD + kb + q * 8]);
    }
}

__global__ void __launch_bounds__(256) k_gemm(int dummy) {
    extern __shared__ char smem[];
    const uint32_t sb = smem_u32(smem);
    const int tid  = threadIdx.x;
    const int lane = tid & 31;
    const int wid  = tid >> 5;
    const int wm   = (wid & 3) * 32;
    const int wn   = (wid >> 2) * 32;
    const int gm   = blockIdx.x * BM;
    const int bn   = blockIdx.y * BN;

    const int a_row  = wm + (lane & 7) + ((lane >> 3) & 1) * 8;
    const int a_colb = (lane >> 4) * 8;
    const int b_row  = wn + (lane & 7) + ((lane >> 4) << 3);
    const int b_colb = ((lane >> 3) & 1) * 8;

    float acc[2][4][4];
    #pragma unroll
    for (int i = 0; i < 2; i++)
        #pragma unroll
        for (int j = 0; j < 4; j++)
            #pragma unroll
            for (int q = 0; q < 4; q++) acc[i][j][q] = 0.0f;

    #pragma unroll
    for (int s = 0; s < NSTAGE - 1; s++) {
        load_stage(sb + s * STAGE_B, gm, bn, s * BK, tid);
        asm volatile("cp.async.commit_group;" ::: "memory");
    }

    for (int c = 0; c < NKIT; ++c) {
        asm volatile("cp.async.wait_group %0;" :: "n"(NSTAGE - 2) : "memory");
        __syncthreads();

        if (c + NSTAGE - 1 < NKIT)
            load_stage(sb + ((c + NSTAGE - 1) & (NSTAGE - 1)) * STAGE_B,
                       gm, bn, (c + NSTAGE - 1) * BK, tid);
        asm volatile("cp.async.commit_group;" ::: "memory");

        const uint32_t st = sb + (c & (NSTAGE - 1)) * STAGE_B;
        #pragma unroll
        for (int ks = 0; ks < 2; ++ks) {
            uint32_t aF[2][4], bF[2][4];
            #pragma unroll
            for (int mt = 0; mt < 2; ++mt)
                ldm_x4(aF[mt], st + OFF_A + ((a_row + mt * 16) * SROW + ks * 16 + a_colb) * 2);
            #pragma unroll
            for (int ng = 0; ng < 2; ++ng)
                ldm_x4(bF[ng], st + OFF_B + ((b_row + ng * 16) * SROW + ks * 16 + b_colb) * 2);
            #pragma unroll
            for (int mt = 0; mt < 2; ++mt) {
                #pragma unroll
                for (int j = 0; j < 4; ++j) {
                    int g = j >> 1, p = (j & 1) * 2;
                    mma_fp16(acc[mt][j], aF[mt], bF[g][p], bF[g][p + 1]);
                }
            }
        }
        __syncthreads();
    }

    const int gid = lane >> 2, tig = lane & 3;
    #pragma unroll
    for (int mt = 0; mt < 2; ++mt) {
        int r0 = gm + wm + mt * 16 + gid;
        #pragma unroll
        for (int j = 0; j < 4; ++j) {
            int col = bn + wn + j * 8 + tig * 2;
            if (r0 < NN)
                *(float2*)(g_xw + (size_t)r0 * NDP + col) =
                    make_float2(acc[mt][j][0], acc[mt][j][1]);
            if (r0 + 8 < NN)
                *(float2*)(g_xw + (size_t)(r0 + 8) * NDP + col) =
                    make_float2(acc[mt][j][2], acc[mt][j][3]);
        }
    }
}

// ---------------- fused aggregation + ReLU + embeddings + tiled broadcast ----
// one block per node: gather phase hits L2, store phase streams to DRAM;
// phases of different blocks overlap across waves.
__global__ void __launch_bounds__(320) k_agg_bcast(const float* __restrict__ b,
                                                   float* __restrict__ out) {
    __shared__ float sh[ND];
    const int n = blockIdx.x;
    const int c = threadIdx.x;   // 0..319 (pad cols of g_xw are zero)

    const float dn = g_dis[n];
    float acc = g_xw[(size_t)n * NDP + c] * (dn * dn);   // self loop
    const int p0 = g_off[n], p1 = g_off[n + 1];
    for (int p = p0; p < p1; ++p)
        acc += g_xw[(size_t)g_src[p] * NDP + c] * g_nrm[p];

    if (c < ND) {
        float hv = fmaxf(acc + b[c], 0.0f);
        sh[c] = hv;
        __stcs(out + EMB_OFF + (size_t)n * ND + c, hv);
    }
    __syncthreads();

    float4* op = (float4*)(out + (size_t)n * TILE_PER_NODE);
    for (int i = c; i < TILE_PER_NODE / 4; i += 320) {
        int g = i / 3;          // (h*301 + cc)
        int cc = g % ND;
        float v = sh[cc];
        __stcs(op + i, make_float4(v, v, v, v));
    }
}

// ---------------- launch ----------------
extern "C" void kernel_launch(void* const* d_in, const int* in_sizes, int n_in,
                              void* d_out, int out_size) {
    const float* x  = (const float*)d_in[0];
    const void*  ei = d_in[1];
    const float* ew = (const float*)d_in[2];
    const float* W  = (const float*)d_in[4];
    const float* b  = (const float*)d_in[5];
    float*       out = (float*)d_out;

    static cudaStream_t s2;
    static cudaEvent_t e1, e2;
    static int init_done = 0;
    if (!init_done) {
        cudaFuncSetAttribute(k_gemm, cudaFuncAttributeMaxDynamicSharedMemorySize, GEMM_SMEM);
        cudaStreamCreateWithFlags(&s2, cudaStreamNonBlocking);
        cudaEventCreateWithFlags(&e1, cudaEventDisableTiming);
        cudaEventCreateWithFlags(&e2, cudaEventDisableTiming);
        init_done = 1;
    }

    // fork: CSR chain on s2
    cudaEventRecord(e1, 0);
    cudaStreamWaitEvent(s2, e1, 0);
    k_detect_init<<<(NN + 255) / 256, 256, 0, s2>>>(ei);
    k_degcnt<<<(NE + 255) / 256, 256, 0, s2>>>(ei, ew);
    k_scan  <<<1, 1024, 0, s2>>>();
    k_fill  <<<(NE + 255) / 256, 256, 0, s2>>>(ei, ew);
    cudaEventRecord(e2, s2);

    // main: convert + GEMM
    k_convx <<<NN, 256>>>(x);
    k_convw <<<NDP, 256>>>(W);
    k_gemm  <<<dim3((NN + BM - 1) / BM, NDP / BN), 256, GEMM_SMEM>>>(0);

    // join, then fused aggregation + output
    cudaStreamWaitEvent(0, e2, 0);
    k_agg_bcast<<<NN, 320>>>(b, out);
}

// round 10
// speedup vs baseline: 2.6812x; 1.0343x over previous
#include <cuda_runtime.h>
#include <cuda_fp16.h>
#include <cstdint>

// ---------------- problem constants ----------------
#define NN      10000
#define NG      2000
#define ND      301
#define NDP     320        // padded embed dim
#define NE      320000
#define NHEADS  4
#define HDIM    12
#define TILE_PER_NODE (NHEADS * ND * HDIM)            // 14448
#define OUT_TILE_ELEMS ((size_t)NN * TILE_PER_NODE)   // 144,480,000
#define EMB_OFF OUT_TILE_ELEMS

#define KPAD    2048
#define BK      32
#define NKIT    (KPAD / BK)    // 64
#define BM      128
#define BN      64
#define NSTAGE  4

// smem stage layout: rows padded to 40 fp16 (80 B) for conflict-free ldmatrix
#define SROW    40
#define OFF_A   0
#define OFF_B   10240          // 128*40*2
#define STAGE_B 15360          // + 64*40*2
#define GEMM_SMEM (NSTAGE * STAGE_B)   // 61440

// ---------------- device scratch ----------------
__device__ __half g_xh[(size_t)NN * KPAD];    // 41 MB
__device__ __half g_wh[(size_t)NDP * KPAD];   // W^T [n][k]
__device__ __half2 g_xw2[(size_t)NN * (NDP / 2)];   // xw in fp16 pairs (6.4 MB)
__device__ float g_deg[NN];
__device__ float g_dis[NN];
__device__ int   g_cnt[NN];
__device__ int   g_off[NN + 1];
__device__ int   g_cur[NN];
__device__ int   g_src[NE];
__device__ float g_nrm[NE];
__device__ int   g_is64;

// ---------------- small helpers ----------------
__device__ __forceinline__ uint32_t smem_u32(const void* p) {
    uint32_t a;
    asm("{ .reg .u64 t; cvta.to.shared.u64 t, %1; cvt.u32.u64 %0, t; }" : "=r"(a) : "l"(p));
    return a;
}
__device__ __forceinline__ void cp16(uint32_t saddr, const void* gaddr) {
    asm volatile("cp.async.cg.shared.global [%0], [%1], 16;" :: "r"(saddr), "l"(gaddr));
}
__device__ __forceinline__ void ldm_x4(uint32_t* r, uint32_t addr) {
    asm volatile("ldmatrix.sync.aligned.m8n8.x4.shared.b16 {%0,%1,%2,%3}, [%4];"
        : "=r"(r[0]), "=r"(r[1]), "=r"(r[2]), "=r"(r[3]) : "r"(addr));
}
__device__ __forceinline__ void mma_fp16(float* c, const uint32_t* a,
                                         uint32_t b0, uint32_t b1) {
    asm volatile("mma.sync.aligned.m16n8k16.row.col.f32.f16.f16.f32 "
        "{%0,%1,%2,%3}, {%4,%5,%6,%7}, {%8,%9}, {%0,%1,%2,%3};"
        : "+f"(c[0]), "+f"(c[1]), "+f"(c[2]), "+f"(c[3])
        : "r"(a[0]), "r"(a[1]), "r"(a[2]), "r"(a[3]), "r"(b0), "r"(b1));
}

// ---------------- edge-index dtype + init (merged) ----------------
__global__ void k_detect_init(const void* __restrict__ ei) {
    __shared__ int bad;
    int i = blockIdx.x * blockDim.x + threadIdx.x;
    if (i < NN) { g_deg[i] = 1.0f; g_cnt[i] = 0; }
    if (blockIdx.x == 0) {
        if (threadIdx.x == 0) bad = 0;
        __syncthreads();
        const long long* p = (const long long*)ei;
        for (int k = threadIdx.x; k < 4096; k += blockDim.x) {
            long long v = p[k];
            if (v < 0 || v >= NN) bad = 1;
        }
        __syncthreads();
        if (threadIdx.x == 0) g_is64 = bad ? 0 : 1;
    }
}
__device__ __forceinline__ int edge_at(const void* __restrict__ ei, int pos) {
    int v = g_is64 ? (int)((const long long*)ei)[pos] : ((const int*)ei)[pos];
    return v < 0 ? 0 : (v >= NN ? NN - 1 : v);
}

// ---------------- CSR build ----------------
__global__ void k_degcnt(const void* __restrict__ ei, const float* __restrict__ ew) {
    int e = blockIdx.x * blockDim.x + threadIdx.x;
    if (e >= NE) return;
    int c = edge_at(ei, NE + e);
    atomicAdd(&g_deg[c], ew[e]);
    atomicAdd(&g_cnt[c], 1);
}

// shfl-based single-block scan + dis = rsqrt(deg)
__global__ void k_scan() {
    __shared__ int wsum[32];
    const int t = threadIdx.x;
    const int lane = t & 31, warp = t >> 5;
    const int base = t * 10;
    int loc[10];
    int s = 0;
    #pragma unroll
    for (int j = 0; j < 10; j++) {
        int idx = base + j;
        int v = (idx < NN) ? g_cnt[idx] : 0;
        loc[j] = s; s += v;
    }
    int inc = s;
    #pragma unroll
    for (int o = 1; o < 32; o <<= 1) {
        int n = __shfl_up_sync(0xFFFFFFFF, inc, o);
        if (lane >= o) inc += n;
    }
    if (lane == 31) wsum[warp] = inc;
    __syncthreads();
    if (warp == 0) {
        int w = wsum[lane];
        #pragma unroll
        for (int o = 1; o < 32; o <<= 1) {
            int n = __shfl_up_sync(0xFFFFFFFF, w, o);
            if (lane >= o) w += n;
        }
        wsum[lane] = w;
    }
    __syncthreads();
    int pre = inc - s + (warp ? wsum[warp - 1] : 0);
    #pragma unroll
    for (int j = 0; j < 10; j++) {
        int idx = base + j;
        if (idx < NN) { int o = pre + loc[j]; g_off[idx] = o; g_cur[idx] = o; }
    }
    if (t == 1023) g_off[NN] = wsum[31];
    #pragma unroll
    for (int r = 0; r < 10; r++) {
        int i = t + r * 1024;
        if (i < NN) g_dis[i] = rsqrtf(g_deg[i]);
    }
}
__global__ void k_fill(const void* __restrict__ ei, const float* __restrict__ ew) {
    int e = blockIdx.x * blockDim.x + threadIdx.x;
    if (e >= NE) return;
    int r = edge_at(ei, e);
    int c = edge_at(ei, NE + e);
    int slot = atomicAdd(&g_cur[c], 1);
    slot = slot < 0 ? 0 : (slot >= NE ? NE - 1 : slot);
    g_src[slot] = r;
    g_nrm[slot] = g_dis[r] * ew[e] * g_dis[c];
}

// ---------------- fp32 -> fp16 conversion ----------------
__global__ void __launch_bounds__(256) k_convx(const float* __restrict__ x) {
    int row = blockIdx.x;
    int col = threadIdx.x * 8;
    float a[8];
    if (col + 8 <= NG) {
        const float4* p = (const float4*)(x + (size_t)row * NG + col);
        float4 v0 = p[0], v1 = p[1];
        a[0] = v0.x; a[1] = v0.y; a[2] = v0.z; a[3] = v0.w;
        a[4] = v1.x; a[5] = v1.y; a[6] = v1.z; a[7] = v1.w;
    } else {
        #pragma unroll
        for (int j = 0; j < 8; j++)
            a[j] = (col + j < NG) ? x[(size_t)row * NG + col + j] : 0.0f;
    }
    unsigned short h[8];
    #pragma unroll
    for (int j = 0; j < 8; j++) {
        __half v = __float2half_rn(a[j]);
        h[j] = *(unsigned short*)&v;
    }
    *(uint4*)(&g_xh[(size_t)row * KPAD + col]) = *(uint4*)h;
}
__global__ void __launch_bounds__(256) k_convw(const float* __restrict__ W) {
    int n = blockIdx.x;
    for (int k = threadIdx.x; k < KPAD; k += 256) {
        float v = (n < ND && k < NG) ? W[(size_t)k * ND + n] : 0.0f;
        g_wh[(size_t)n * KPAD + k] = __float2half_rn(v);
    }
}

// ---------------- mma.sync fp16 GEMM, 4-stage cp.async pipeline ----------------
__device__ __forceinline__ void load_stage(uint32_t sbase, int gm, int bn, int kb, int tid) {
    #pragma unroll
    for (int g = 0; g < 2; g++) {
        int idx = tid + g * 256;
        int row = idx >> 2, q = idx & 3;
        int gr = gm + row; if (gr >= NN) gr = NN - 1;
        cp16(sbase + OFF_A + (row * SROW + q * 8) * 2,
             &g_xh[(size_t)gr * KPAD + kb + q * 8]);
    }
    {
        int row = tid >> 2, q = tid & 3;
        cp16(sbase + OFF_B + (row * SROW + q * 8) * 2,
             &g_wh[(size_t)(bn + row) * KPAD + kb + q * 8]);
    }
}

__global__ void __launch_bounds__(256) k_gemm(int dummy) {
    extern __shared__ char smem[];
    const uint32_t sb = smem_u32(smem);
    const int tid  = threadIdx.x;
    const int lane = tid & 31;
    const int wid  = tid >> 5;
    const int wm   = (wid & 3) * 32;
    const int wn   = (wid >> 2) * 32;
    const int gm   = blockIdx.x * BM;
    const int bn   = blockIdx.y * BN;

    const int a_row  = wm + (lane & 7) + ((lane >> 3) & 1) * 8;
    const int a_colb = (lane >> 4) * 8;
    const int b_row  = wn + (lane & 7) + ((lane >> 4) << 3);
    const int b_colb = ((lane >> 3) & 1) * 8;

    float acc[2][4][4];
    #pragma unroll
    for (int i = 0; i < 2; i++)
        #pragma unroll
        for (int j = 0; j < 4; j++)
            #pragma unroll
            for (int q = 0; q < 4; q++) acc[i][j][q] = 0.0f;

    #pragma unroll
    for (int s = 0; s < NSTAGE - 1; s++) {
        load_stage(sb + s * STAGE_B, gm, bn, s * BK, tid);
        asm volatile("cp.async.commit_group;" ::: "memory");
    }

    for (int c = 0; c < NKIT; ++c) {
        asm volatile("cp.async.wait_group %0;" :: "n"(NSTAGE - 2) : "memory");
        __syncthreads();

        if (c + NSTAGE - 1 < NKIT)
            load_stage(sb + ((c + NSTAGE - 1) & (NSTAGE - 1)) * STAGE_B,
                       gm, bn, (c + NSTAGE - 1) * BK, tid);
        asm volatile("cp.async.commit_group;" ::: "memory");

        const uint32_t st = sb + (c & (NSTAGE - 1)) * STAGE_B;
        #pragma unroll
        for (int ks = 0; ks < 2; ++ks) {
            uint32_t aF[2][4], bF[2][4];
            #pragma unroll
            for (int mt = 0; mt < 2; ++mt)
                ldm_x4(aF[mt], st + OFF_A + ((a_row + mt * 16) * SROW + ks * 16 + a_colb) * 2);
            #pragma unroll
            for (int ng = 0; ng < 2; ++ng)
                ldm_x4(bF[ng], st + OFF_B + ((b_row + ng * 16) * SROW + ks * 16 + b_colb) * 2);
            #pragma unroll
            for (int mt = 0; mt < 2; ++mt) {
                #pragma unroll
                for (int j = 0; j < 4; ++j) {
                    int g = j >> 1, p = (j & 1) * 2;
                    mma_fp16(acc[mt][j], aF[mt], bF[g][p], bF[g][p + 1]);
                }
            }
        }
        __syncthreads();
    }

    // epilogue: fragment -> g_xw2 (fp16 pairs; col is always even)
    const int gid = lane >> 2, tig = lane & 3;
    #pragma unroll
    for (int mt = 0; mt < 2; ++mt) {
        int r0 = gm + wm + mt * 16 + gid;
        #pragma unroll
        for (int j = 0; j < 4; ++j) {
            int col = bn + wn + j * 8 + tig * 2;
            if (r0 < NN)
                g_xw2[(size_t)r0 * (NDP / 2) + col / 2] =
                    __floats2half2_rn(acc[mt][j][0], acc[mt][j][1]);
            if (r0 + 8 < NN)
                g_xw2[(size_t)(r0 + 8) * (NDP / 2) + col / 2] =
                    __floats2half2_rn(acc[mt][j][2], acc[mt][j][3]);
        }
    }
}

// ---------------- fused aggregation + ReLU + embeddings + tiled broadcast ----
// 2 nodes per block, 320 threads: two 160-thread groups gather one node each
// (one half2 per thread per edge), then the whole block streams both tiles.
__global__ void __launch_bounds__(320) k_agg_bcast(const float* __restrict__ b,
                                                   float* __restrict__ out) {
    __shared__ float sh[2][NDP];   // sized to padded dim: pad lanes stay in-bounds
    const int tid = threadIdx.x;
    const int grp = tid / 160;        // 0 or 1
    const int t   = tid % 160;        // channel pair index
    const int n   = blockIdx.x * 2 + grp;

    // gather (fp16 xw, fp32 accumulate)
    {
        const float dn = g_dis[n];
        const __half2* xw = g_xw2 + t;
        float2 v0 = __half22float2(xw[(size_t)n * 160]);
        float2 acc = make_float2(v0.x * dn * dn, v0.y * dn * dn);
        const int p0 = g_off[n], p1 = g_off[n + 1];
        for (int p = p0; p < p1; ++p) {
            float wn = g_nrm[p];
            float2 v = __half22float2(xw[(size_t)g_src[p] * 160]);
            acc.x += v.x * wn;
            acc.y += v.y * wn;
        }
        int c0 = 2 * t;
        if (c0 < ND) {   // guard BOTH halves: c0 reaches 318 > 300 on pad lanes
            float h0 = fmaxf(acc.x + b[c0], 0.0f);
            sh[grp][c0] = h0;
            __stcs(out + EMB_OFF + (size_t)n * ND + c0, h0);
        }
        if (c0 + 1 < ND) {
            float h1 = fmaxf(acc.y + b[c0 + 1], 0.0f);
            sh[grp][c0 + 1] = h1;
            __stcs(out + EMB_OFF + (size_t)n * ND + c0 + 1, h1);
        }
    }
    __syncthreads();

    // broadcast both tiles (float4 splat)
    #pragma unroll
    for (int gg = 0; gg < 2; ++gg) {
        float4* op = (float4*)(out + (size_t)(blockIdx.x * 2 + gg) * TILE_PER_NODE);
        for (int i = tid; i < TILE_PER_NODE / 4; i += 320) {
            int g = i / 3;          // (h*301 + cc)
            int cc = g % ND;
            float v = sh[gg][cc];
            __stcs(op + i, make_float4(v, v, v, v));
        }
    }
}

// ---------------- launch ----------------
extern "C" void kernel_launch(void* const* d_in, const int* in_sizes, int n_in,
                              void* d_out, int out_size) {
    const float* x  = (const float*)d_in[0];
    const void*  ei = d_in[1];
    const float* ew = (const float*)d_in[2];
    const float* W  = (const float*)d_in[4];
    const float* b  = (const float*)d_in[5];
    float*       out = (float*)d_out;

    static cudaStream_t s2;
    static cudaEvent_t e1, e2;
    static int init_done = 0;
    if (!init_done) {
        cudaFuncSetAttribute(k_gemm, cudaFuncAttributeMaxDynamicSharedMemorySize, GEMM_SMEM);
        cudaStreamCreateWithFlags(&s2, cudaStreamNonBlocking);
        cudaEventCreateWithFlags(&e1, cudaEventDisableTiming);
        cudaEventCreateWithFlags(&e2, cudaEventDisableTiming);
        init_done = 1;
    }

    // fork: CSR chain on s2
    cudaEventRecord(e1, 0);
    cudaStreamWaitEvent(s2, e1, 0);
    k_detect_init<<<(NN + 255) / 256, 256, 0, s2>>>(ei);
    k_degcnt<<<(NE + 255) / 256, 256, 0, s2>>>(ei, ew);
    k_scan  <<<1, 1024, 0, s2>>>();
    k_fill  <<<(NE + 255) / 256, 256, 0, s2>>>(ei, ew);
    cudaEventRecord(e2, s2);

    // main: convert + GEMM
    k_convx <<<NN, 256>>>(x);
    k_convw <<<NDP, 256>>>(W);
    k_gemm  <<<dim3((NN + BM - 1) / BM, NDP / BN), 256, GEMM_SMEM>>>(0);

    // join, then fused aggregation + output
    cudaStreamWaitEvent(0, e2, 0);
    k_agg_bcast<<<NN / 2, 320>>>(b, out);
}